// round 2
// baseline (speedup 1.0000x reference)
#include <cuda_runtime.h>
#include <math.h>

// Problem constants
#define DD 512
#define AA 256
#define BB 256

// DEPTHS = linspace(0, 50, 512) -> step h = 50/511
// ANGLES = linspace(-30, 30, 256) -> step 60/255
// P = exp(-(diff^2)/(2*0.5^2)) = exp(-2*diff^2), masked by 0 < d_theory < 50,
// normalized over the depth axis per (b, angle) column.

__global__ void __launch_bounds__(AA, 8)
prior_kernel(const float* __restrict__ p,
             const float* __restrict__ pc,
             float* __restrict__ out)
{
    const int b     = blockIdx.x;   // 0..255
    const int which = blockIdx.y;   // 0 = p, 1 = p_calib
    const int a     = threadIdx.x;  // angle index 0..255

    const float* src = which ? pc : p;
    const float d_val   = src[b * 3 + 1];
    const float theta_p = src[b * 3 + 2];

    const float DEG2RAD   = 0.017453292519943295f; // pi/180
    const float ANG_STEP  = 60.0f / 255.0f;
    const float H         = 50.0f / 511.0f;        // depth step
    const float INV_H     = 511.0f / 50.0f;
    const float CUTOFF    = 5.0f;                  // exp(-2*25) = 2e-22, negligible

    const float angle = (theta_p + (-30.0f + (float)a * ANG_STEP)) * DEG2RAD;
    // accurate cosf: __cosf's ~1e-6 abs error amplifies through the Gaussian
    // slope to near the 1e-3 rel-err gate; one cosf per thread is free.
    const float t = d_val / cosf(angle);

    const bool valid = (t > 0.0f) && (t < 50.0f);

    float* outp = out + ((size_t)which * BB + (size_t)b) * (size_t)(DD * AA) + a;

    if (!valid) {
        // whole column is zero (col_sum==0 -> denom=1 -> P=0)
        #pragma unroll 8
        for (int di = 0; di < DD; ++di)
            outp[(size_t)di * AA] = 0.0f;
        return;
    }

    // Nonzero window of the Gaussian in depth-bin space
    int lo = (int)ceilf((t - CUTOFF) * INV_H);
    int hi = (int)floorf((t + CUTOFF) * INV_H);
    lo = max(lo, 0);
    hi = min(hi, DD - 1);

    // Pass 1: windowed column sum
    float sum = 0.0f;
    for (int di = lo; di <= hi; ++di) {
        float diff = (float)di * H - t;
        sum += __expf(-2.0f * diff * diff);
    }
    const float inv = (sum > 0.0f) ? (1.0f / sum) : 1.0f;

    // Pass 2: write full column; exp only inside the window.
    // Warp writes are 128B contiguous per depth row (thread index == angle).
    #pragma unroll 4
    for (int di = 0; di < DD; ++di) {
        float v = 0.0f;
        if (di >= lo && di <= hi) {
            float diff = (float)di * H - t;
            v = __expf(-2.0f * diff * diff) * inv;
        }
        outp[(size_t)di * AA] = v;
    }
}

extern "C" void kernel_launch(void* const* d_in, const int* in_sizes, int n_in,
                              void* d_out, int out_size)
{
    const float* p  = (const float*)d_in[0];
    const float* pc = (const float*)d_in[1];
    float* out = (float*)d_out;

    dim3 grid(BB, 2);
    dim3 block(AA);
    prior_kernel<<<grid, block>>>(p, pc, out);
}

// round 4
// speedup vs baseline: 1.1135x; 1.1135x over previous
#include <cuda_runtime.h>
#include <math.h>

#define DD 512
#define AA 256
#define BB 256
#define DSPLIT 2                             // grid.z
#define ROWS_PER_BLOCK (DD / DSPLIT)         // 256
#define ROWS_PER_THREAD (ROWS_PER_BLOCK / 4) // 64

// DEPTHS = linspace(0,50,512) -> h = 50/511
// ANGLES = linspace(-30,30,256) -> step 60/255
// P = exp(-2*diff^2), masked by 0 < d/cos < 50, normalized over depth per column.
// exp(-2 z^2) = 2^(C2 * z^2), C2 = -2/ln2. MUFU EX2 with .ftz underflows to
// exact 0 outside ~|z|>4.6, so no window predicate is needed in the write loop.

__device__ __forceinline__ float ex2_ftz(float x) {
    float r;
    asm("ex2.approx.ftz.f32 %0, %1;" : "=f"(r) : "f"(x));
    return r;
}

__global__ void __launch_bounds__(256, 8)
prior_kernel(const float* __restrict__ p,
             const float* __restrict__ pc,
             float* __restrict__ out)
{
    __shared__ float s_t[AA];
    __shared__ float s_inv[AA];

    const int b     = blockIdx.x;   // 0..255
    const int which = blockIdx.y;   // 0 = p, 1 = p_calib
    const int tid   = threadIdx.x;  // 0..255

    const float DEG2RAD  = 0.017453292519943295f;
    const float ANG_STEP = 60.0f / 255.0f;
    const float H        = 50.0f / 511.0f;
    const float INV_H    = 511.0f / 50.0f;
    const float C2       = -2.8853900817779268f;  // -2 / ln(2)

    // ---- Precompute per-angle t and 1/colsum (thread tid <-> angle tid) ----
    {
        const float* src = which ? pc : p;
        const float d_val   = src[b * 3 + 1];
        const float theta_p = src[b * 3 + 2];

        const float angle = (theta_p + (-30.0f + (float)tid * ANG_STEP)) * DEG2RAD;
        const float t = d_val / cosf(angle);   // accurate cosf (error amplifies
                                               // through the Gaussian slope)
        const bool valid = (t > 0.0f) && (t < 50.0f);

        float inv = 0.0f;
        if (valid) {
            // windowed sum: tail beyond |diff|=5 contributes < 1e-21
            int lo = max((int)ceilf((t - 5.0f) * INV_H), 0);
            int hi = min((int)floorf((t + 5.0f) * INV_H), DD - 1);
            float sum = 0.0f;
            for (int di = lo; di <= hi; ++di) {
                float z = (float)di * H - t;
                sum += ex2_ftz(C2 * z * z);
            }
            inv = (sum > 0.0f) ? (1.0f / sum) : 1.0f;
        }
        s_t[tid]   = t;
        s_inv[tid] = inv;
    }
    __syncthreads();

    // ---- Write phase: thread owns 4 angles x 64 depth rows, STG.128 per row ----
    const int aq   = tid & 63;          // angle quad: angles 4*aq .. 4*aq+3
    const int dsub = tid >> 6;          // 0..3
    const int d0   = blockIdx.z * ROWS_PER_BLOCK + dsub * ROWS_PER_THREAD;

    const int a0 = aq * 4;
    const float t0 = s_t[a0 + 0], t1 = s_t[a0 + 1], t2 = s_t[a0 + 2], t3 = s_t[a0 + 3];
    const float i0 = s_inv[a0 + 0], i1 = s_inv[a0 + 1], i2 = s_inv[a0 + 2], i3 = s_inv[a0 + 3];

    float z0 = (float)d0 * H - t0;
    float z1 = (float)d0 * H - t1;
    float z2 = (float)d0 * H - t2;
    float z3 = (float)d0 * H - t3;

    float4* outp = (float4*)(out
        + (((size_t)which * BB + b) * DD + d0) * (size_t)AA + a0);
    const int row_stride = AA / 4;      // float4 units per depth row

    #pragma unroll 4
    for (int r = 0; r < ROWS_PER_THREAD; ++r) {
        float4 v;
        v.x = ex2_ftz(C2 * z0 * z0) * i0;
        v.y = ex2_ftz(C2 * z1 * z1) * i1;
        v.z = ex2_ftz(C2 * z2 * z2) * i2;
        v.w = ex2_ftz(C2 * z3 * z3) * i3;
        outp[(size_t)r * row_stride] = v;
        z0 += H; z1 += H; z2 += H; z3 += H;
    }
}

extern "C" void kernel_launch(void* const* d_in, const int* in_sizes, int n_in,
                              void* d_out, int out_size)
{
    const float* p  = (const float*)d_in[0];
    const float* pc = (const float*)d_in[1];
    float* out = (float*)d_out;

    dim3 grid(BB, 2, DSPLIT);
    dim3 block(256);
    prior_kernel<<<grid, block>>>(p, pc, out);
}